// round 15
// baseline (speedup 1.0000x reference)
#include <cuda_runtime.h>

// FittedRankOneRNN via 1-D coefficient tables + cubic Taylor in p.
//   x_t = p_t*m + q_t*wi (x0=0);  q_{t+1}=0.8q_t+0.2u_t (input-only!);
//   p_{t+1}=0.8p_t+f(p_t,q_t);  z_{t-1}=g(p_t,q_t)
//   f = sum_k p^k/k! Fk(q),  Fk(q)=0.2/N sum n m^k T_k(q wi)   (g likewise, w)
// Fk,Gk tabulated on 1024 q-nodes, linear in q. Depth-2 software pipeline:
// the (clamp/cvt/LDS) lookup for step t+2 is issued at step t, with the
// q-interp pre-mixed at lookup time, so the in-loop p-critical path is just
// two 3-fma Horner chains + the p update.
// R14 failed on an off-by-one in the u prefetch (u_{tc+3} instead of u_{tc+2})
// introduced by the reshape; fixed here, all else identical.

#define NQ      1024
#define QLO     (-2.5f)
#define QSTEP   (5.0f / 1023.0f)
#define QSCL    (1023.0f / 5.0f)
#define QBIAS   (-QLO * QSCL)

__device__ float4 d_coef[2 * NQ];   // [2j]=f c0..c3, [2j+1]=g c0..c3; 32 KB

__device__ __forceinline__ float x_ex2(float v) {
    float r; asm("ex2.approx.f32 %0, %1;" : "=f"(r) : "f"(v)); return r;
}
__device__ __forceinline__ float x_rcp(float v) {
    float r; asm("rcp.approx.f32 %0, %1;" : "=f"(r) : "f"(v)); return r;
}
__device__ __forceinline__ float x_tanh(float v) {
    const float t = x_ex2(v * 2.8853900817779268f);
    return (t - 1.0f) * x_rcp(t + 1.0f);
}

// ---------- stage 1: tabulate Taylor coefficient functions of q ----------
__global__ __launch_bounds__(256)
void tab_kernel(const float* __restrict__ gm,
                const float* __restrict__ gn,
                const float* __restrict__ gwi,
                const float* __restrict__ gw)
{
    __shared__ float red[8][8];
    const int   node = blockIdx.x;
    const float qv   = QLO + (float)node * QSTEP;

    const int tid  = threadIdx.x;
    const int lane = tid & 31;
    const int wrp  = tid >> 5;

    float a[8] = {0.f, 0.f, 0.f, 0.f, 0.f, 0.f, 0.f, 0.f};  // f0..f3, g0..g3
#pragma unroll
    for (int e = 0; e < 4; e++) {
        const int i = tid + e * 256;
        const float th = x_tanh(qv * gwi[i]);
        const float sc = 1.0f - th * th;
        const float d0 = th;
        const float d1 = sc;                                      // T1
        const float d2 = -th * sc;                                // T2/2
        const float d3 = sc * (3.0f * th * th - 1.0f) * (1.0f / 3.0f);  // T3/6
        const float m1 = gm[i], m2 = m1 * m1, m3 = m2 * m1;
        const float nv = gn[i], wv = gw[i];
        a[0] = fmaf(nv,      d0, a[0]);  a[4] = fmaf(wv,      d0, a[4]);
        a[1] = fmaf(nv * m1, d1, a[1]);  a[5] = fmaf(wv * m1, d1, a[5]);
        a[2] = fmaf(nv * m2, d2, a[2]);  a[6] = fmaf(wv * m2, d2, a[6]);
        a[3] = fmaf(nv * m3, d3, a[3]);  a[7] = fmaf(wv * m3, d3, a[7]);
    }
#pragma unroll
    for (int off = 16; off; off >>= 1) {
#pragma unroll
        for (int k = 0; k < 8; k++)
            a[k] += __shfl_xor_sync(0xffffffffu, a[k], off);
    }
    if (lane == 0) {
#pragma unroll
        for (int k = 0; k < 8; k++) red[wrp][k] = a[k];
    }
    __syncthreads();
    if (tid < 8) {
        float acc = 0.f;
#pragma unroll
        for (int wp = 0; wp < 8; wp++) acc += red[wp][tid];
        const float scl = (tid < 4) ? (0.2f / 1024.0f) : (1.0f / 1024.0f);
        ((float*)&d_coef[2 * node])[tid] = acc * scl;
    }
}

// ---------- stage 2: scalar recurrence with depth-2 pipelined lookup ----------
__device__ __forceinline__ void fetch_mix(const float4* __restrict__ tab,
                                          float qv, float4* cf, float4* cg)
{
    const float xq = fminf(fmaxf(fmaf(qv, QSCL, QBIAS), 0.0f), 1022.99f);
    const int   qi = (int)xq;
    const float fr = xq - (float)qi;
    const float4 fa = tab[2 * qi],     ga = tab[2 * qi + 1];
    const float4 fb = tab[2 * qi + 2], gb = tab[2 * qi + 3];
    cf->x = fmaf(fr, fb.x - fa.x, fa.x);
    cf->y = fmaf(fr, fb.y - fa.y, fa.y);
    cf->z = fmaf(fr, fb.z - fa.z, fa.z);
    cf->w = fmaf(fr, fb.w - fa.w, fa.w);
    cg->x = fmaf(fr, gb.x - ga.x, ga.x);
    cg->y = fmaf(fr, gb.y - ga.y, ga.y);
    cg->z = fmaf(fr, gb.z - ga.z, ga.z);
    cg->w = fmaf(fr, gb.w - ga.w, ga.w);
}

__global__ __launch_bounds__(32)
void scan_kernel(const float* __restrict__ gu, float* __restrict__ gz, int T)
{
    __shared__ float4 tab[2 * NQ];     // 32 KB table copy
    const int lane = threadIdx.x;
    for (int i = lane; i < 2 * NQ; i += 32) tab[i] = d_coef[i];
    __syncwarp();

    const int bb = blockIdx.x * 32 + lane;
    const float* __restrict__ uin = gu + bb * T;
    float* __restrict__ zout = gz + bb * T;

    float pst = 0.f;
    float4 cf[2], cg[2];

    // prologue: ready sets for steps 0 (q_0 = 0) and 1 (q_1 = 0.2 u_0)
    fetch_mix(tab, 0.0f, &cf[0], &cg[0]);
    float qlead = 0.2f * uin[0];                  // q_1
    fetch_mix(tab, qlead, &cf[1], &cg[1]);
    float ulead = uin[1];                         // u_1, forms q_2 at tc=0

    for (int t = 0; t < T; t += 2) {
#pragma unroll
        for (int s = 0; s < 2; s++) {
            const int tc = t + s;
            // advance q one step (to q_{tc+2}) and refill ulead with u_{tc+2}
            const float un = ulead;                              // u_{tc+1}
            ulead = uin[(tc + 2 < T) ? (tc + 2) : (T - 1)];      // u_{tc+2}
            const float qn = fmaf(0.8f, qlead, 0.2f * un);       // q_{tc+2}
            qlead = qn;
            // evaluate current step from the ready slot
            const float4 f4 = cf[s], g4 = cg[s];
            const float fv = fmaf(fmaf(fmaf(f4.w, pst, f4.z), pst, f4.y), pst, f4.x);
            const float gv = fmaf(fmaf(fmaf(g4.w, pst, g4.z), pst, g4.y), pst, g4.x);
            if (tc > 0) zout[tc - 1] = gv;        // z_{t-1} = g(p_t, q_t)
            pst = fmaf(0.8f, pst, fv);
            fetch_mix(tab, qn, &cf[s], &cg[s]);   // lookup for step tc+2
        }
    }
    // slot 0 holds step-T coefficients (fetched at tc = T-2)
    zout[T - 1] = fmaf(fmaf(fmaf(cg[0].w, pst, cg[0].z), pst, cg[0].y), pst, cg[0].x);
}

// ---------- launcher ----------
extern "C" void kernel_launch(void* const* d_in, const int* in_sizes, int n_in,
                              void* d_out, int out_size)
{
    const float* u  = (const float*)d_in[0];
    const float* m  = (const float*)d_in[1];
    const float* n  = (const float*)d_in[2];
    const float* wi = (const float*)d_in[3];
    const float* w  = (const float*)d_in[4];
    float* z = (float*)d_out;

    const int T = 1000;
    const int B = out_size / T;          // 256

    tab_kernel<<<NQ, 256>>>(m, n, wi, w);
    scan_kernel<<<B / 32, 32>>>(u, z, T);
}

// round 17
// speedup vs baseline: 1.6757x; 1.6757x over previous
#include <cuda_runtime.h>

// FittedRankOneRNN via 1-D coefficient tables + cubic Taylor in p.
//   x_t = p_t*m + q_t*wi (x0=0);  q_{t+1}=0.8q_t+0.2u_t (input-only!);
//   p_{t+1}=0.8p_t+f(p_t,q_t);  z_{t-1}=g(p_t,q_t)
//   f = sum_k p^k/k! Fk(q),  Fk(q)=0.2/N sum n m^k T_k(q wi)   (g likewise, w)
// Fk,Gk on 1024 q-nodes, linear interp in q; depth-2 pipelined lookup.
// R15 lesson: per-step 4B LDG/STG on 4000B-strided rows = 32 L1 wavefronts per
// warp access = LSU-bound. Time grouped in 4s: one LDG.128 of u[4j..4j+3] per
// lane (one group ahead) and one STG.128 of z[4j..4j+3] -> 4x fewer wavefronts,
// 4x deeper miss-prefetch window. (R16 = container failure; cosmetic reshape
// only — same logic, renamed symbols.)

#define NQ      1024
#define QLO     (-2.5f)
#define QSTEP   (5.0f / 1023.0f)
#define QSCL    (1023.0f / 5.0f)
#define QBIAS   (-QLO * QSCL)

__device__ float4 c_tab[2 * NQ];    // [2j]=f c0..c3, [2j+1]=g c0..c3; 32 KB

__device__ __forceinline__ float i_ex2(float v) {
    float r; asm("ex2.approx.f32 %0, %1;" : "=f"(r) : "f"(v)); return r;
}
__device__ __forceinline__ float i_rcp(float v) {
    float r; asm("rcp.approx.f32 %0, %1;" : "=f"(r) : "f"(v)); return r;
}
__device__ __forceinline__ float i_tanh(float v) {
    const float t = i_ex2(v * 2.8853900817779268f);
    return (t - 1.0f) * i_rcp(t + 1.0f);
}

// q-lookup with the q-interp pre-mixed into one coefficient set per function.
__device__ __forceinline__ void coef_fetch(const float4* __restrict__ tab,
                                           float qv, float4* cf, float4* cg)
{
    const float xq = fminf(fmaxf(fmaf(qv, QSCL, QBIAS), 0.0f), 1022.99f);
    const int   qi = (int)xq;
    const float fr = xq - (float)qi;
    const float4 fa = tab[2 * qi],     ga = tab[2 * qi + 1];
    const float4 fb = tab[2 * qi + 2], gb = tab[2 * qi + 3];
    cf->x = fmaf(fr, fb.x - fa.x, fa.x);
    cf->y = fmaf(fr, fb.y - fa.y, fa.y);
    cf->z = fmaf(fr, fb.z - fa.z, fa.z);
    cf->w = fmaf(fr, fb.w - fa.w, fa.w);
    cg->x = fmaf(fr, gb.x - ga.x, ga.x);
    cg->y = fmaf(fr, gb.y - ga.y, ga.y);
    cg->z = fmaf(fr, gb.z - ga.z, ga.z);
    cg->w = fmaf(fr, gb.w - ga.w, ga.w);
}

// ---------- stage 1: tabulate Taylor coefficient functions of q ----------
__global__ __launch_bounds__(256)
void coef_build(const float* __restrict__ gm,
                const float* __restrict__ gn,
                const float* __restrict__ gwi,
                const float* __restrict__ gw)
{
    __shared__ float red[8][8];
    const int   node = blockIdx.x;
    const float qv   = QLO + (float)node * QSTEP;

    const int tid  = threadIdx.x;
    const int lane = tid & 31;
    const int wrp  = tid >> 5;

    float a[8] = {0.f, 0.f, 0.f, 0.f, 0.f, 0.f, 0.f, 0.f};  // f0..f3, g0..g3
#pragma unroll
    for (int e = 0; e < 4; e++) {
        const int i = tid + e * 256;
        const float th = i_tanh(qv * gwi[i]);
        const float sc = 1.0f - th * th;
        const float d0 = th;
        const float d1 = sc;                                        // T1
        const float d2 = -th * sc;                                  // T2/2
        const float d3 = sc * (3.0f * th * th - 1.0f) * (1.0f / 3.0f);  // T3/6
        const float m1 = gm[i], m2 = m1 * m1, m3 = m2 * m1;
        const float nv = gn[i], wv = gw[i];
        a[0] = fmaf(nv,      d0, a[0]);  a[4] = fmaf(wv,      d0, a[4]);
        a[1] = fmaf(nv * m1, d1, a[1]);  a[5] = fmaf(wv * m1, d1, a[5]);
        a[2] = fmaf(nv * m2, d2, a[2]);  a[6] = fmaf(wv * m2, d2, a[6]);
        a[3] = fmaf(nv * m3, d3, a[3]);  a[7] = fmaf(wv * m3, d3, a[7]);
    }
#pragma unroll
    for (int off = 16; off; off >>= 1) {
#pragma unroll
        for (int k = 0; k < 8; k++)
            a[k] += __shfl_xor_sync(0xffffffffu, a[k], off);
    }
    if (lane == 0) {
#pragma unroll
        for (int k = 0; k < 8; k++) red[wrp][k] = a[k];
    }
    __syncthreads();
    if (tid < 8) {
        float acc = 0.f;
#pragma unroll
        for (int wp = 0; wp < 8; wp++) acc += red[wp][tid];
        const float scl = (tid < 4) ? (0.2f / 1024.0f) : (1.0f / 1024.0f);
        ((float*)&c_tab[2 * node])[tid] = acc * scl;
    }
}

// ---------- stage 2: scalar recurrence, vectorized u/z + pipelined lookup ----------
__global__ __launch_bounds__(32)
void rnn_scan(const float* __restrict__ gu, float* __restrict__ gz, int T)
{
    __shared__ float4 tab[2 * NQ];     // 32 KB table copy
    const int lane = threadIdx.x;
    for (int i = lane; i < 2 * NQ; i += 32) tab[i] = c_tab[i];
    __syncwarp();

    const int bb = blockIdx.x * 32 + lane;
    const float4* __restrict__ uin4  = (const float4*)(gu + bb * T);  // 4000B rows: 16B aligned
    float4* __restrict__       zout4 = (float4*)(gz + bb * T);
    const int NG = T >> 2;             // 250 groups of 4 steps

    float pst = 0.f;
    float4 cf[2], cg[2];
    float z0 = 0.f, z1 = 0.f, z2 = 0.f;

    // u group buffers: ucur = group j, unxt = group j+1 (LDG.128, ~4 steps slack)
    float4 ucur = uin4[0];
    float4 unxt = uin4[1];

    // prologue: coefficient slots for steps 0 (q_0=0) and 1 (q_1=0.2*u_0)
    coef_fetch(tab, 0.0f, &cf[0], &cg[0]);
    float qlead = 0.2f * ucur.x;                   // q_1
    coef_fetch(tab, qlead, &cf[1], &cg[1]);

    for (int j = 0; j < NG; j++) {
#pragma unroll
        for (int s = 0; s < 4; s++) {
            // u_{tc+1}, tc = 4j+s: comps 1..3 of ucur for s=0..2; comp 0 of unxt for s=3
            const float un = (s == 0) ? ucur.y : (s == 1) ? ucur.z
                           : (s == 2) ? ucur.w : unxt.x;
            const float qn = fmaf(0.8f, qlead, 0.2f * un);   // q_{tc+2}
            qlead = qn;
            // evaluate step tc from ready slot (tc & 1 == s & 1)
            const float4 f4 = cf[s & 1], g4 = cg[s & 1];
            const float fv = fmaf(fmaf(fmaf(f4.w, pst, f4.z), pst, f4.y), pst, f4.x);
            const float gv = fmaf(fmaf(fmaf(g4.w, pst, g4.z), pst, g4.y), pst, g4.x);
            // z[tc-1]: s=0 completes the previous group -> one STG.128
            if (s == 0) {
                if (j > 0) zout4[j - 1] = make_float4(z0, z1, z2, gv);
            } else if (s == 1) z0 = gv;
            else if (s == 2)   z1 = gv;
            else               z2 = gv;
            pst = fmaf(0.8f, pst, fv);
            coef_fetch(tab, qn, &cf[s & 1], &cg[s & 1]);     // refill for step tc+2
        }
        // rotate u groups; prefetch group j+2
        ucur = unxt;
        unxt = uin4[(j + 2 < NG) ? (j + 2) : (NG - 1)];
    }
    // step T: slot 0 (fetched at tc = T-2) holds q_T coefficients
    const float4 g4 = cg[0];
    const float gfin = fmaf(fmaf(fmaf(g4.w, pst, g4.z), pst, g4.y), pst, g4.x);
    zout4[NG - 1] = make_float4(z0, z1, z2, gfin);
}

// ---------- launcher ----------
extern "C" void kernel_launch(void* const* d_in, const int* in_sizes, int n_in,
                              void* d_out, int out_size)
{
    const float* u  = (const float*)d_in[0];
    const float* m  = (const float*)d_in[1];
    const float* n  = (const float*)d_in[2];
    const float* wi = (const float*)d_in[3];
    const float* w  = (const float*)d_in[4];
    float* z = (float*)d_out;

    const int T = 1000;
    const int B = out_size / T;          // 256

    coef_build<<<NQ, 256>>>(m, n, wi, w);
    rnn_scan<<<B / 32, 32>>>(u, z, T);
}